// round 1
// baseline (speedup 1.0000x reference)
#include <cuda_runtime.h>
#include <math.h>

// Problem dims
#define BB  128
#define TT  31
#define TP1 32
#define EE  512
#define HH  512
#define H4  2048
#define VV  10000
#define AA  2048
#define LDW_ATTN 1024   // W_attn row stride (H+E)
#define LDW_ATTD 2560   // W_attd row stride (A+E)

// ---------------- device scratch (static, no allocs) ----------------
__device__ float g_xs   [TP1*BB*EE];   // [t][b][e] inputs (features at t=0, emb after)
__device__ float g_hid  [TP1*BB*HH];   // [t][b][h] hidden history
__device__ float g_h    [BB*HH];
__device__ float g_c    [BB*HH];
__device__ float g_attnx[TT*BB*AA];    // x_t @ W_attn[:, :E].T  for t=1..31
__device__ float g_attdx[TT*BB*EE];    // x_t @ W_attd[:, :E].T + b_attd
__device__ float g_alog [BB*AA];       // attention logits
__device__ float g_att  [BB*AA];       // attended features
__device__ float g_x2   [BB*EE];       // projected lstm input
__device__ float g_gates[BB*H4];       // lstm gates

// ---------------- kernels ----------------

__global__ void build_xs_kernel(const float* __restrict__ features,
                                const int*   __restrict__ captions,
                                const float* __restrict__ table,
                                float* __restrict__ xs)
{
    int idx = blockIdx.x * blockDim.x + threadIdx.x;
    const int total = TP1 * BB * EE;
    if (idx >= total) return;
    int e = idx % EE;
    int b = (idx / EE) % BB;
    int t = idx / (EE * BB);
    float v;
    if (t == 0) {
        v = features[b * EE + e];
    } else {
        int tok = captions[b * TT + (t - 1)];
        v = table[tok * EE + e];
    }
    xs[idx] = v;
}

__global__ void zero_kernel(float* __restrict__ p, int n)
{
    int idx = blockIdx.x * blockDim.x + threadIdx.x;
    if (idx < n) p[idx] = 0.0f;
}

// Generic tiled GEMM: C[m,n] = sum_k A[m,k]*W[n,k] (+bias0[n]) (+bias1[n]) (+add[m,n])
template<int BM, int BN, int BK, int TM, int TN>
__global__ void gemm_kernel(const float* __restrict__ A, int lda,
                            const float* __restrict__ W, int ldw,
                            const float* __restrict__ bias0,
                            const float* __restrict__ bias1,
                            const float* __restrict__ add, int ldadd,
                            float* __restrict__ C, int ldc,
                            int M, int N, int K)
{
    constexpr int THREADS = (BM / TM) * (BN / TN);
    __shared__ float As[BK][BM + 1];
    __shared__ float Ws[BK][BN + 1];

    const int bm = blockIdx.y * BM;
    const int bn = blockIdx.x * BN;
    const int tid = threadIdx.x;
    const int tx = tid % (BN / TN);
    const int ty = tid / (BN / TN);

    float acc[TM][TN];
    #pragma unroll
    for (int i = 0; i < TM; i++)
        #pragma unroll
        for (int j = 0; j < TN; j++) acc[i][j] = 0.0f;

    for (int k0 = 0; k0 < K; k0 += BK) {
        #pragma unroll
        for (int i = tid; i < BM * BK; i += THREADS) {
            int r = i / BK, c = i % BK;
            int gm = bm + r;
            As[c][r] = (gm < M) ? A[(size_t)gm * lda + (k0 + c)] : 0.0f;
        }
        #pragma unroll
        for (int i = tid; i < BN * BK; i += THREADS) {
            int r = i / BK, c = i % BK;
            int gn = bn + r;
            Ws[c][r] = (gn < N) ? W[(size_t)gn * ldw + (k0 + c)] : 0.0f;
        }
        __syncthreads();
        #pragma unroll
        for (int k = 0; k < BK; k++) {
            float a[TM], w[TN];
            #pragma unroll
            for (int i = 0; i < TM; i++) a[i] = As[k][ty * TM + i];
            #pragma unroll
            for (int j = 0; j < TN; j++) w[j] = Ws[k][tx * TN + j];
            #pragma unroll
            for (int i = 0; i < TM; i++)
                #pragma unroll
                for (int j = 0; j < TN; j++)
                    acc[i][j] = fmaf(a[i], w[j], acc[i][j]);
        }
        __syncthreads();
    }

    #pragma unroll
    for (int i = 0; i < TM; i++) {
        int gm = bm + ty * TM + i;
        if (gm >= M) continue;
        #pragma unroll
        for (int j = 0; j < TN; j++) {
            int gn = bn + tx * TN + j;
            if (gn >= N) continue;
            float v = acc[i][j];
            if (bias0) v += bias0[gn];
            if (bias1) v += bias1[gn];
            if (add)   v += add[(size_t)gm * ldadd + gn];
            C[(size_t)gm * ldc + gn] = v;
        }
    }
}

// Fused softmax over 2048 + elementwise attend: att = cnn * softmax(logits)
__global__ void softmax_attend_kernel(const float* __restrict__ logits,
                                      const float* __restrict__ cnn,
                                      float* __restrict__ att)
{
    const int b = blockIdx.x;
    const int tid = threadIdx.x;     // 256 threads
    const float* row = logits + (size_t)b * AA;
    __shared__ float red[256];

    float v[8];
    float mx = -1e30f;
    #pragma unroll
    for (int j = 0; j < 8; j++) {
        v[j] = row[tid + j * 256];
        mx = fmaxf(mx, v[j]);
    }
    red[tid] = mx;
    __syncthreads();
    for (int s = 128; s > 0; s >>= 1) {
        if (tid < s) red[tid] = fmaxf(red[tid], red[tid + s]);
        __syncthreads();
    }
    mx = red[0];
    __syncthreads();

    float sum = 0.0f;
    #pragma unroll
    for (int j = 0; j < 8; j++) {
        v[j] = expf(v[j] - mx);
        sum += v[j];
    }
    red[tid] = sum;
    __syncthreads();
    for (int s = 128; s > 0; s >>= 1) {
        if (tid < s) red[tid] += red[tid + s];
        __syncthreads();
    }
    float inv = 1.0f / red[0];

    const float* crow = cnn + (size_t)b * AA;
    float* arow = att + (size_t)b * AA;
    #pragma unroll
    for (int j = 0; j < 8; j++) {
        int col = tid + j * 256;
        arow[col] = crow[col] * v[j] * inv;
    }
}

__device__ __forceinline__ float sigmoidf_(float x) {
    return 1.0f / (1.0f + expf(-x));
}

// Pointwise LSTM: consumes gates [B,4H] (i,f,g,o), updates h,c, writes hid_t
__global__ void lstm_pointwise_kernel(const float* __restrict__ gates,
                                      float* __restrict__ h,
                                      float* __restrict__ c,
                                      float* __restrict__ hid_t)
{
    int idx = blockIdx.x * blockDim.x + threadIdx.x;
    if (idx >= BB * HH) return;
    int b = idx / HH, n = idx % HH;
    const float* g = gates + (size_t)b * H4;
    float ig = sigmoidf_(g[n]);
    float fg = sigmoidf_(g[HH + n]);
    float gg = tanhf(g[2 * HH + n]);
    float og = sigmoidf_(g[3 * HH + n]);
    float cc = fg * c[idx] + ig * gg;
    float hh = og * tanhf(cc);
    c[idx] = cc;
    h[idx] = hh;
    hid_t[idx] = hh;
}

// ---------------- host ----------------

static inline void launch_gemm_big(const float* A, int lda, const float* W, int ldw,
                                   const float* b0, const float* b1,
                                   const float* add, int ldadd,
                                   float* C, int ldc, int M, int N, int K)
{
    dim3 grid((N + 63) / 64, (M + 127) / 128);
    gemm_kernel<128, 64, 16, 8, 4><<<grid, 256>>>(A, lda, W, ldw, b0, b1, add, ldadd, C, ldc, M, N, K);
}

static inline void launch_gemm_small(const float* A, int lda, const float* W, int ldw,
                                     const float* b0, const float* b1,
                                     const float* add, int ldadd,
                                     float* C, int ldc, int M, int N, int K)
{
    dim3 grid((N + 63) / 64, (M + 31) / 32);
    gemm_kernel<32, 64, 16, 2, 4><<<grid, 256>>>(A, lda, W, ldw, b0, b1, add, ldadd, C, ldc, M, N, K);
}

extern "C" void kernel_launch(void* const* d_in, const int* in_sizes, int n_in,
                              void* d_out, int out_size)
{
    const float* features = (const float*)d_in[0];   // [B,E]
    const float* cnn      = (const float*)d_in[1];   // [B,A]
    const int*   captions = (const int*)  d_in[2];   // [B,T]
    // d_in[3] lengths unused
    const float* table    = (const float*)d_in[4];   // [V,E]
    const float* W_ih     = (const float*)d_in[5];   // [4H,E]
    const float* W_hh     = (const float*)d_in[6];   // [4H,H]
    const float* b_ih     = (const float*)d_in[7];
    const float* b_hh     = (const float*)d_in[8];
    const float* W_attn   = (const float*)d_in[9];   // [A,H+E]
    const float* b_attn   = (const float*)d_in[10];
    const float* W_attd   = (const float*)d_in[11];  // [E,A+E]
    const float* b_attd   = (const float*)d_in[12];
    const float* W_out    = (const float*)d_in[13];  // [V,H]
    const float* b_out    = (const float*)d_in[14];
    float* out = (float*)d_out;                      // [(T+1)*B, V]

    float *p_xs, *p_hid, *p_h, *p_c, *p_attnx, *p_attdx, *p_alog, *p_att, *p_x2, *p_gates;
    cudaGetSymbolAddress((void**)&p_xs,    g_xs);
    cudaGetSymbolAddress((void**)&p_hid,   g_hid);
    cudaGetSymbolAddress((void**)&p_h,     g_h);
    cudaGetSymbolAddress((void**)&p_c,     g_c);
    cudaGetSymbolAddress((void**)&p_attnx, g_attnx);
    cudaGetSymbolAddress((void**)&p_attdx, g_attdx);
    cudaGetSymbolAddress((void**)&p_alog,  g_alog);
    cudaGetSymbolAddress((void**)&p_att,   g_att);
    cudaGetSymbolAddress((void**)&p_x2,    g_x2);
    cudaGetSymbolAddress((void**)&p_gates, g_gates);

    // 1) Build xs = [features ; embed(captions)]  -> [T+1][B][E]
    {
        int total = TP1 * BB * EE;
        build_xs_kernel<<<(total + 255) / 256, 256>>>(features, captions, table, p_xs);
    }
    // 2) Zero c
    zero_kernel<<<(BB * HH + 255) / 256, 256>>>(p_c, BB * HH);

    // 3) Precompute x-dependent attention terms for t=1..T (batched, parallel)
    //    attnx = xs[1:] @ W_attn[:, :E].T            [T*B, A]
    launch_gemm_big(p_xs + BB * EE, EE, W_attn, LDW_ATTN,
                    nullptr, nullptr, nullptr, 0,
                    p_attnx, AA, TT * BB, AA, EE);
    //    attdx = xs[1:] @ W_attd[:, :E].T + b_attd   [T*B, E]
    launch_gemm_big(p_xs + BB * EE, EE, W_attd, LDW_ATTD,
                    b_attd, nullptr, nullptr, 0,
                    p_attdx, EE, TT * BB, EE, EE);

    // 4) t = 0: gates = xs[0] @ W_ih.T + b_ih + b_hh  (h=0 so skip W_hh)
    launch_gemm_small(p_xs, EE, W_ih, EE,
                      b_ih, b_hh, nullptr, 0,
                      p_gates, H4, BB, H4, EE);
    lstm_pointwise_kernel<<<(BB * HH + 255) / 256, 256>>>(p_gates, p_h, p_c, p_hid);

    // 5) Recurrent loop t = 1..T
    for (int t = 1; t <= TT; t++) {
        const float* attnx_t = p_attnx + (size_t)(t - 1) * BB * AA;
        const float* attdx_t = p_attdx + (size_t)(t - 1) * BB * EE;

        // attention logits = attnx_t + h @ W_attn[:, E:].T + b_attn
        launch_gemm_small(p_h, HH, W_attn + EE, LDW_ATTN,
                          b_attn, nullptr, attnx_t, AA,
                          p_alog, AA, BB, AA, HH);
        // softmax + attend
        softmax_attend_kernel<<<BB, 256>>>(p_alog, cnn, p_att);
        // x2 = attdx_t + attended @ W_attd[:, E:].T
        launch_gemm_small(p_att, AA, W_attd + EE, LDW_ATTD,
                          nullptr, nullptr, attdx_t, EE,
                          p_x2, EE, BB, EE, AA);
        // gates = x2 @ W_ih.T + b_ih + b_hh
        launch_gemm_small(p_x2, EE, W_ih, EE,
                          b_ih, b_hh, nullptr, 0,
                          p_gates, H4, BB, H4, EE);
        // gates += h @ W_hh.T
        launch_gemm_small(p_h, HH, W_hh, HH,
                          nullptr, nullptr, p_gates, H4,
                          p_gates, H4, BB, H4, HH);
        // LSTM pointwise, write hidden[t]
        lstm_pointwise_kernel<<<(BB * HH + 255) / 256, 256>>>(
            p_gates, p_h, p_c, p_hid + (size_t)t * BB * HH);
    }

    // 6) Output projection: logits = hidden @ W_out.T + b_out   [(T+1)*B, V]
    launch_gemm_big(p_hid, HH, W_out, HH,
                    b_out, nullptr, nullptr, 0,
                    out, VV, TP1 * BB, VV, HH);
}

// round 2
// speedup vs baseline: 4.2383x; 4.2383x over previous
#include <cuda_runtime.h>
#include <math.h>

// Problem dims
#define BB  128
#define TT  31
#define TP1 32
#define EE  512
#define HH  512
#define H4  2048
#define VV  10000
#define AA  2048

// ---------------- device scratch (static, no allocs) ----------------
__device__ float g_xs   [TP1*BB*EE];    // [t][b][e]
__device__ float g_hid  [TP1*BB*HH];    // [t][b][h]
__device__ float g_c    [BB*HH];
__device__ float g_xh   [BB*1024];      // [b][0:512]=x2, [b][512:1024]=h
__device__ float g_attnx[TT*BB*AA];     // x_t @ W_attn[:, :E].T
__device__ float g_attdx[TT*BB*EE];     // x_t @ W_attd[:, :E].T + b_attd
__device__ float g_alogp[2*BB*AA];      // attn logit split-K partials
__device__ float g_att  [BB*AA];        // attended
__device__ float g_x2p  [8*BB*EE];      // x2 split-K partials
__device__ float g_gp   [4*BB*H4];      // gate split-K partials
__device__ float g_Wcat [H4*1024];      // [W_ih | W_hh] packed

// ---------------- setup kernels ----------------

__global__ void build_xs_kernel(const float* __restrict__ features,
                                const int*   __restrict__ captions,
                                const float* __restrict__ table,
                                float* __restrict__ xs)
{
    int idx = blockIdx.x * blockDim.x + threadIdx.x;
    const int total = TP1 * BB * EE;
    if (idx >= total) return;
    int e = idx % EE;
    int b = (idx / EE) % BB;
    int t = idx / (EE * BB);
    float v;
    if (t == 0) v = features[b * EE + e];
    else {
        int tok = captions[b * TT + (t - 1)];
        v = table[tok * EE + e];
    }
    xs[idx] = v;
}

__global__ void pack_wcat_kernel(const float* __restrict__ Wih,
                                 const float* __restrict__ Whh,
                                 float* __restrict__ Wcat)
{
    int idx = blockIdx.x * blockDim.x + threadIdx.x;
    if (idx >= H4 * 1024) return;
    int n = idx / 1024, k = idx % 1024;
    Wcat[idx] = (k < 512) ? Wih[n * 512 + k] : Whh[n * 512 + (k - 512)];
}

__global__ void init_state_kernel(const float* __restrict__ features,
                                  float* __restrict__ xh,
                                  float* __restrict__ c)
{
    int idx = blockIdx.x * blockDim.x + threadIdx.x;
    if (idx < BB * 1024) {
        int b = idx / 1024, k = idx % 1024;
        xh[idx] = (k < 512) ? features[b * 512 + k] : 0.0f;
    }
    if (idx < BB * HH) c[idx] = 0.0f;
}

// ---------------- big GEMM: 128x128 tile, 8x8/thread, float4 ----------------
// C[m,n] = sum_k A[m,k] * W[n,k] (+bias[n]).  M multiple of 128, K multiple of 16.
__global__ void __launch_bounds__(256, 2)
gemm_big_kernel(const float* __restrict__ A, int lda,
                const float* __restrict__ W, int ldw,
                const float* __restrict__ bias,
                float* __restrict__ C, int ldc,
                int N, int K)
{
    __shared__ float As[16][132];
    __shared__ float Ws[16][132];
    const int bm = blockIdx.y * 128;
    const int bn = blockIdx.x * 128;
    const int tid = threadIdx.x;
    const int tx = tid % 16;     // 16 x TN8 = 128
    const int ty = tid / 16;     // 16 x TM8 = 128

    float acc[8][8];
    #pragma unroll
    for (int i = 0; i < 8; i++)
        #pragma unroll
        for (int j = 0; j < 8; j++) acc[i][j] = 0.0f;

    for (int k0 = 0; k0 < K; k0 += 16) {
        #pragma unroll
        for (int i = 0; i < 2; i++) {
            int idx = tid + i * 256;         // float4 index (512 total)
            int row = idx >> 2;
            int kq  = idx & 3;
            float4 v = *(const float4*)(A + (size_t)(bm + row) * lda + k0 + kq * 4);
            As[kq*4+0][row] = v.x; As[kq*4+1][row] = v.y;
            As[kq*4+2][row] = v.z; As[kq*4+3][row] = v.w;
            int gn = bn + row;
            float4 u = make_float4(0.f, 0.f, 0.f, 0.f);
            if (gn < N) u = *(const float4*)(W + (size_t)gn * ldw + k0 + kq * 4);
            Ws[kq*4+0][row] = u.x; Ws[kq*4+1][row] = u.y;
            Ws[kq*4+2][row] = u.z; Ws[kq*4+3][row] = u.w;
        }
        __syncthreads();
        #pragma unroll
        for (int k = 0; k < 16; k++) {
            float4 a0 = *(const float4*)&As[k][ty * 8];
            float4 a1 = *(const float4*)&As[k][ty * 8 + 4];
            float4 w0 = *(const float4*)&Ws[k][tx * 8];
            float4 w1 = *(const float4*)&Ws[k][tx * 8 + 4];
            float av[8] = {a0.x,a0.y,a0.z,a0.w,a1.x,a1.y,a1.z,a1.w};
            float wv[8] = {w0.x,w0.y,w0.z,w0.w,w1.x,w1.y,w1.z,w1.w};
            #pragma unroll
            for (int i = 0; i < 8; i++)
                #pragma unroll
                for (int j = 0; j < 8; j++)
                    acc[i][j] = fmaf(av[i], wv[j], acc[i][j]);
        }
        __syncthreads();
    }

    const bool hasb = (bias != nullptr);
    #pragma unroll
    for (int i = 0; i < 8; i++) {
        int gm = bm + ty * 8 + i;
        #pragma unroll
        for (int j = 0; j < 8; j++) {
            int gn = bn + tx * 8 + j;
            if (gn < N)
                C[(size_t)gm * ldc + gn] = acc[i][j] + (hasb ? bias[gn] : 0.0f);
        }
    }
}

// ---------------- step GEMM: 64x64 tile, 4x8/thread, split-K -> partials ----
// Cpart[z][m][n] = sum_{k in [z*Ksplit,(z+1)*Ksplit)} A[m,k]*W[n,k]
// All dims exact multiples; no guards.
__global__ void __launch_bounds__(128)
gemm_step_kernel(const float* __restrict__ A, int lda,
                 const float* __restrict__ W, int ldw,
                 float* __restrict__ Cpart, int ldc, size_t pstride,
                 int Ksplit)
{
    __shared__ float As[16][68];
    __shared__ float Ws[16][68];
    const int bm = blockIdx.y * 64;
    const int bn = blockIdx.x * 64;
    const int kb = blockIdx.z * Ksplit;
    float* C = Cpart + blockIdx.z * pstride;
    const int tid = threadIdx.x;
    const int tx = tid & 7;      // 8 x TN8 = 64
    const int ty = tid >> 3;     // 16 x TM4 = 64

    float acc[4][8];
    #pragma unroll
    for (int i = 0; i < 4; i++)
        #pragma unroll
        for (int j = 0; j < 8; j++) acc[i][j] = 0.0f;

    for (int k0 = 0; k0 < Ksplit; k0 += 16) {
        #pragma unroll
        for (int i = 0; i < 2; i++) {
            int idx = tid + i * 128;        // float4 index (256 total)
            int row = idx >> 2;
            int kq  = idx & 3;
            float4 v = *(const float4*)(A + (size_t)(bm + row) * lda + kb + k0 + kq * 4);
            As[kq*4+0][row] = v.x; As[kq*4+1][row] = v.y;
            As[kq*4+2][row] = v.z; As[kq*4+3][row] = v.w;
            float4 u = *(const float4*)(W + (size_t)(bn + row) * ldw + kb + k0 + kq * 4);
            Ws[kq*4+0][row] = u.x; Ws[kq*4+1][row] = u.y;
            Ws[kq*4+2][row] = u.z; Ws[kq*4+3][row] = u.w;
        }
        __syncthreads();
        #pragma unroll
        for (int k = 0; k < 16; k++) {
            float4 a0 = *(const float4*)&As[k][ty * 4];
            float4 w0 = *(const float4*)&Ws[k][tx * 8];
            float4 w1 = *(const float4*)&Ws[k][tx * 8 + 4];
            float av[4] = {a0.x,a0.y,a0.z,a0.w};
            float wv[8] = {w0.x,w0.y,w0.z,w0.w,w1.x,w1.y,w1.z,w1.w};
            #pragma unroll
            for (int i = 0; i < 4; i++)
                #pragma unroll
                for (int j = 0; j < 8; j++)
                    acc[i][j] = fmaf(av[i], wv[j], acc[i][j]);
        }
        __syncthreads();
    }

    #pragma unroll
    for (int i = 0; i < 4; i++) {
        int gm = bm + ty * 4 + i;
        float4 s0 = make_float4(acc[i][0], acc[i][1], acc[i][2], acc[i][3]);
        float4 s1 = make_float4(acc[i][4], acc[i][5], acc[i][6], acc[i][7]);
        *(float4*)(C + (size_t)gm * ldc + bn + tx * 8)     = s0;
        *(float4*)(C + (size_t)gm * ldc + bn + tx * 8 + 4) = s1;
    }
}

// ---------------- softmax + attend (combines 2 split-K partials) -----------
__global__ void softmax_attend_kernel(const float* __restrict__ p0,
                                      const float* __restrict__ p1,
                                      const float* __restrict__ attnx,
                                      const float* __restrict__ b_attn,
                                      const float* __restrict__ cnn,
                                      float* __restrict__ att)
{
    const int b = blockIdx.x;
    const int tid = threadIdx.x;     // 256
    __shared__ float red[256];

    float v[8];
    float mx = -1e30f;
    #pragma unroll
    for (int j = 0; j < 8; j++) {
        int col = tid + j * 256;
        size_t o = (size_t)b * AA + col;
        v[j] = p0[o] + p1[o] + attnx[o] + b_attn[col];
        mx = fmaxf(mx, v[j]);
    }
    red[tid] = mx;
    __syncthreads();
    for (int s = 128; s > 0; s >>= 1) {
        if (tid < s) red[tid] = fmaxf(red[tid], red[tid + s]);
        __syncthreads();
    }
    mx = red[0];
    __syncthreads();

    float sum = 0.0f;
    #pragma unroll
    for (int j = 0; j < 8; j++) { v[j] = expf(v[j] - mx); sum += v[j]; }
    red[tid] = sum;
    __syncthreads();
    for (int s = 128; s > 0; s >>= 1) {
        if (tid < s) red[tid] += red[tid + s];
        __syncthreads();
    }
    float inv = 1.0f / red[0];

    #pragma unroll
    for (int j = 0; j < 8; j++) {
        int col = tid + j * 256;
        size_t o = (size_t)b * AA + col;
        att[o] = cnn[o] * v[j] * inv;
    }
}

// ---------------- x2 combine: 8 partials + attdx -> xh[:, :512] ------------
__global__ void combine_x2_kernel(const float* __restrict__ parts,
                                  const float* __restrict__ attdx,
                                  float* __restrict__ xh)
{
    int idx = blockIdx.x * blockDim.x + threadIdx.x;
    if (idx >= BB * EE) return;
    int b = idx / EE, e = idx % EE;
    float s = attdx[idx];
    #pragma unroll
    for (int p = 0; p < 8; p++) s += parts[(size_t)p * BB * EE + idx];
    xh[b * 1024 + e] = s;
}

// ---------------- LSTM pointwise (combines 4 gate partials) ----------------
__device__ __forceinline__ float sigmoidf_(float x) {
    return 1.0f / (1.0f + expf(-x));
}

__global__ void lstm_pointwise_kernel(const float* __restrict__ gp,
                                      const float* __restrict__ b_ih,
                                      const float* __restrict__ b_hh,
                                      float* __restrict__ xh,
                                      float* __restrict__ c,
                                      float* __restrict__ hid_t)
{
    int idx = blockIdx.x * blockDim.x + threadIdx.x;
    if (idx >= BB * HH) return;
    int b = idx / HH, n = idx % HH;
    float gi = b_ih[n]        + b_hh[n];
    float gf = b_ih[512 + n]  + b_hh[512 + n];
    float gg = b_ih[1024 + n] + b_hh[1024 + n];
    float go = b_ih[1536 + n] + b_hh[1536 + n];
    #pragma unroll
    for (int p = 0; p < 4; p++) {
        const float* base = gp + (size_t)p * BB * H4 + (size_t)b * H4;
        gi += base[n];
        gf += base[512 + n];
        gg += base[1024 + n];
        go += base[1536 + n];
    }
    gi = sigmoidf_(gi);
    gf = sigmoidf_(gf);
    gg = tanhf(gg);
    go = sigmoidf_(go);
    float cc = gf * c[idx] + gi * gg;
    float hh = go * tanhf(cc);
    c[idx] = cc;
    xh[b * 1024 + 512 + n] = hh;
    hid_t[idx] = hh;
}

// ---------------- host ----------------

extern "C" void kernel_launch(void* const* d_in, const int* in_sizes, int n_in,
                              void* d_out, int out_size)
{
    const float* features = (const float*)d_in[0];
    const float* cnn      = (const float*)d_in[1];
    const int*   captions = (const int*)  d_in[2];
    const float* table    = (const float*)d_in[4];
    const float* W_ih     = (const float*)d_in[5];
    const float* W_hh     = (const float*)d_in[6];
    const float* b_ih     = (const float*)d_in[7];
    const float* b_hh     = (const float*)d_in[8];
    const float* W_attn   = (const float*)d_in[9];
    const float* b_attn   = (const float*)d_in[10];
    const float* W_attd   = (const float*)d_in[11];
    const float* b_attd   = (const float*)d_in[12];
    const float* W_out    = (const float*)d_in[13];
    const float* b_out    = (const float*)d_in[14];
    float* out = (float*)d_out;

    float *p_xs, *p_hid, *p_c, *p_xh, *p_attnx, *p_attdx,
          *p_alogp, *p_att, *p_x2p, *p_gp, *p_Wcat;
    cudaGetSymbolAddress((void**)&p_xs,    g_xs);
    cudaGetSymbolAddress((void**)&p_hid,   g_hid);
    cudaGetSymbolAddress((void**)&p_c,     g_c);
    cudaGetSymbolAddress((void**)&p_xh,    g_xh);
    cudaGetSymbolAddress((void**)&p_attnx, g_attnx);
    cudaGetSymbolAddress((void**)&p_attdx, g_attdx);
    cudaGetSymbolAddress((void**)&p_alogp, g_alogp);
    cudaGetSymbolAddress((void**)&p_att,   g_att);
    cudaGetSymbolAddress((void**)&p_x2p,   g_x2p);
    cudaGetSymbolAddress((void**)&p_gp,    g_gp);
    cudaGetSymbolAddress((void**)&p_Wcat,  g_Wcat);

    // Setup
    build_xs_kernel<<<(TP1*BB*EE + 255)/256, 256>>>(features, captions, table, p_xs);
    pack_wcat_kernel<<<(H4*1024 + 255)/256, 256>>>(W_ih, W_hh, p_Wcat);
    init_state_kernel<<<(BB*1024 + 255)/256, 256>>>(features, p_xh, p_c);

    // Precompute x-dependent attention terms (batched over t=1..31)
    // attnx = xs[1:] @ W_attn[:, :E].T       [3968, 2048]
    gemm_big_kernel<<<dim3(AA/128, (TT*BB)/128), 256>>>(
        p_xs + BB*EE, EE, W_attn, 1024, nullptr, p_attnx, AA, AA, EE);
    // attdx = xs[1:] @ W_attd[:, :E].T + b_attd   [3968, 512]
    gemm_big_kernel<<<dim3(EE/128, (TT*BB)/128), 256>>>(
        p_xs + BB*EE, EE, W_attd, 2560, b_attd, p_attdx, EE, EE, EE);

    // t = 0: gates = [features|0] @ Wcat.T  (split-K4), then LSTM
    gemm_step_kernel<<<dim3(H4/64, BB/64, 4), 128>>>(
        p_xh, 1024, p_Wcat, 1024, p_gp, H4, (size_t)BB*H4, 256);
    lstm_pointwise_kernel<<<(BB*HH + 255)/256, 256>>>(
        p_gp, b_ih, b_hh, p_xh, p_c, p_hid);

    // Recurrent loop
    for (int t = 1; t <= TT; t++) {
        const float* attnx_t = p_attnx + (size_t)(t - 1) * BB * AA;
        const float* attdx_t = p_attdx + (size_t)(t - 1) * BB * EE;

        // attn logits partials: h @ W_attn[:, E:].T  (split-K2)
        gemm_step_kernel<<<dim3(AA/64, BB/64, 2), 128>>>(
            p_xh + 512, 1024, W_attn + EE, 1024, p_alogp, AA, (size_t)BB*AA, 256);
        // softmax + attend (combines partials + attnx + bias)
        softmax_attend_kernel<<<BB, 256>>>(
            p_alogp, p_alogp + BB*AA, attnx_t, b_attn, cnn, p_att);
        // x2 partials: att @ W_attd[:, E:].T  (split-K8)
        gemm_step_kernel<<<dim3(EE/64, BB/64, 8), 128>>>(
            p_att, AA, W_attd + EE, 2560, p_x2p, EE, (size_t)BB*EE, 256);
        // combine into xh[:, :512]
        combine_x2_kernel<<<(BB*EE + 255)/256, 256>>>(p_x2p, attdx_t, p_xh);
        // gates partials: [x2|h] @ Wcat.T  (split-K4)
        gemm_step_kernel<<<dim3(H4/64, BB/64, 4), 128>>>(
            p_xh, 1024, p_Wcat, 1024, p_gp, H4, (size_t)BB*H4, 256);
        // LSTM pointwise
        lstm_pointwise_kernel<<<(BB*HH + 255)/256, 256>>>(
            p_gp, b_ih, b_hh, p_xh, p_c, p_hid + (size_t)t * BB * HH);
    }

    // Output projection: logits = hidden @ W_out.T + b_out  [4096, 10000]
    gemm_big_kernel<<<dim3((VV + 127)/128, (TP1*BB)/128), 256>>>(
        p_hid, HH, W_out, HH, b_out, out, VV, VV, HH);
}

// round 6
// speedup vs baseline: 5.3541x; 1.2633x over previous
#include <cuda_runtime.h>
#include <cuda_bf16.h>
#include <cstdint>
#include <math.h>

// Problem dims
#define BB  128
#define TT  31
#define TP1 32
#define EE  512
#define HH  512
#define H4  2048
#define VV  10000
#define AA  2048
#define MTOT 4096   // (T+1)*B rows

// ---------------- device scratch (static, no allocs) ----------------
__device__ float g_xs   [MTOT*EE];
__device__ float g_hid  [MTOT*HH];
__device__ float g_c    [BB*HH];
__device__ float g_xh   [BB*1024];
__device__ float g_attnx[MTOT*AA];
__device__ float g_attdx[MTOT*EE];
__device__ float g_alogp[2*BB*AA];
__device__ float g_att  [BB*AA];
__device__ float g_x2p  [8*BB*EE];
__device__ float g_gp   [4*BB*H4];
__device__ float g_Wcat [H4*1024];

// bf16 split buffers
__device__ __nv_bfloat16 g_xs_hi [MTOT*EE], g_xs_lo [MTOT*EE];
__device__ __nv_bfloat16 g_hid_hi[MTOT*HH], g_hid_lo[MTOT*HH];
__device__ __nv_bfloat16 g_Woh[VV*HH],  g_Wol[VV*HH];
__device__ __nv_bfloat16 g_Wnh[AA*EE],  g_Wnl[AA*EE];
__device__ __nv_bfloat16 g_Wdh[EE*EE],  g_Wdl[EE*EE];

// ================= warp-MMA helpers (sm_80+ baseline PTX only) =================
__device__ __forceinline__ uint32_t smem_u32(const void* p) {
    uint32_t a;
    asm("{ .reg .u64 t; cvta.to.shared.u64 t, %1; cvt.u32.u64 %0, t; }" : "=r"(a) : "l"(p));
    return a;
}
__device__ __forceinline__ uint32_t sw128(uint32_t b) { return b ^ ((b >> 3) & 0x70); }

__device__ __forceinline__ void ldsm_x4(uint32_t* r, uint32_t addr) {
    asm volatile("ldmatrix.sync.aligned.m8n8.x4.shared.b16 {%0,%1,%2,%3}, [%4];"
                 : "=r"(r[0]), "=r"(r[1]), "=r"(r[2]), "=r"(r[3]) : "r"(addr));
}
__device__ __forceinline__ void ldsm_x2(uint32_t* r, uint32_t addr) {
    asm volatile("ldmatrix.sync.aligned.m8n8.x2.shared.b16 {%0,%1}, [%2];"
                 : "=r"(r[0]), "=r"(r[1]) : "r"(addr));
}
__device__ __forceinline__ void mma16816(float* d, const uint32_t* a, const uint32_t* b) {
    asm volatile("mma.sync.aligned.m16n8k16.row.col.f32.bf16.bf16.f32 "
                 "{%0,%1,%2,%3}, {%4,%5,%6,%7}, {%8,%9}, {%0,%1,%2,%3};"
                 : "+f"(d[0]), "+f"(d[1]), "+f"(d[2]), "+f"(d[3])
                 : "r"(a[0]), "r"(a[1]), "r"(a[2]), "r"(a[3]), "r"(b[0]), "r"(b[1]));
}

// ============ warp-MMA split-bf16 GEMM: C = A@B^T (+bias) ============
// A: [M x K] bf16 hi/lo, M multiple of 128; B: [Ntot x K] bf16 hi/lo (row-guarded);
// K multiple of 64. C: [M x ldc] f32.  3 passes: Ahi*Bhi + Ahi*Blo + Alo*Bhi.
// SMEM tiles (dynamic, 64KB): [0]=Ahi 128x64, [16K]=Alo, [32K]=Bhi 128x64, [48K]=Blo
__global__ void __launch_bounds__(256, 1)
gemm_mma_kernel(const __nv_bfloat16* __restrict__ Ahi,
                const __nv_bfloat16* __restrict__ Alo,
                const __nv_bfloat16* __restrict__ Bhi,
                const __nv_bfloat16* __restrict__ Blo,
                const float* __restrict__ bias,
                float* __restrict__ C, int ldc, int Ntot, int K)
{
    extern __shared__ char smem[];
    const uint32_t sb = smem_u32(smem);
    const int tid = threadIdx.x;
    const int wid = tid >> 5;
    const int lane = tid & 31;
    const int warp_m = wid & 1;        // 2 m-slices of 64
    const int warp_n = wid >> 1;       // 4 n-slices of 32
    const int bm = blockIdx.y * 128;
    const int bn = blockIdx.x * 128;

    float acc[4][4][4];
    #pragma unroll
    for (int i = 0; i < 4; i++)
        #pragma unroll
        for (int j = 0; j < 4; j++)
            #pragma unroll
            for (int r = 0; r < 4; r++) acc[i][j][r] = 0.0f;

    const __nv_bfloat16* srcs[4] = {Ahi, Alo, Bhi, Blo};

    const int nchunks = K >> 6;
    for (int kc = 0; kc < nchunks; kc++) {
        if (kc > 0) __syncthreads();
        // ---- load 4 tiles of 128 rows x 64 bf16 ----
        #pragma unroll
        for (int t = 0; t < 4; t++) {
            const __nv_bfloat16* src = srcs[t];
            const uint32_t dstbase = t * 16384;
            #pragma unroll
            for (int j = 0; j < 4; j++) {
                int v = tid + j * 256;            // 1024 vec16 per tile
                int row = v >> 3, c8 = v & 7;
                uint4 val = make_uint4(0, 0, 0, 0);
                if (t < 2) {
                    val = *(const uint4*)(src + (size_t)(bm + row) * K + kc * 64 + c8 * 8);
                } else {
                    int gn = bn + row;
                    if (gn < Ntot)
                        val = *(const uint4*)(src + (size_t)gn * K + kc * 64 + c8 * 8);
                }
                *(uint4*)(smem + dstbase + sw128(row * 128 + c8 * 16)) = val;
            }
        }
        __syncthreads();

        // ---- 3 passes over loaded tiles ----
        #pragma unroll
        for (int pass = 0; pass < 3; pass++) {
            const uint32_t abase = sb + ((pass == 2) ? 16384 : 0);       // Alo on pass2
            const uint32_t bbase = sb + 32768 + ((pass == 1) ? 16384 : 0); // Blo on pass1
            #pragma unroll
            for (int kk = 0; kk < 4; kk++) {
                // A fragments: 4 m-tiles of 16
                uint32_t afr[4][4];
                #pragma unroll
                for (int mt = 0; mt < 4; mt++) {
                    int row = warp_m * 64 + mt * 16 + (lane & 15);
                    int kb  = kk * 32 + ((lane >> 4) << 4);
                    ldsm_x4(afr[mt], abase + sw128(row * 128 + kb));
                }
                // B fragments: 4 n-tiles of 8
                uint32_t bfr[4][2];
                #pragma unroll
                for (int nt = 0; nt < 4; nt++) {
                    int row = warp_n * 32 + nt * 8 + (lane & 7);
                    int kb  = kk * 32 + (((lane >> 3) & 1) << 4);
                    ldsm_x2(bfr[nt], bbase + sw128(row * 128 + kb));
                }
                #pragma unroll
                for (int mt = 0; mt < 4; mt++)
                    #pragma unroll
                    for (int nt = 0; nt < 4; nt++)
                        mma16816(acc[mt][nt], afr[mt], bfr[nt]);
            }
        }
    }

    // ---- epilogue: direct register -> global ----
    const int gid = lane >> 2;          // 0..7 (row within 8)
    const int tg  = lane & 3;           // 0..3 (col pair)
    #pragma unroll
    for (int mt = 0; mt < 4; mt++) {
        int row0 = bm + warp_m * 64 + mt * 16 + gid;
        #pragma unroll
        for (int nt = 0; nt < 4; nt++) {
            int col = bn + warp_n * 32 + nt * 8 + tg * 2;
            if (col < Ntot) {
                float b0 = bias ? bias[col] : 0.0f;
                float b1 = bias ? bias[col + 1] : 0.0f;
                float2 v0 = make_float2(acc[mt][nt][0] + b0, acc[mt][nt][1] + b1);
                float2 v1 = make_float2(acc[mt][nt][2] + b0, acc[mt][nt][3] + b1);
                *(float2*)(C + (size_t)row0 * ldc + col) = v0;
                *(float2*)(C + (size_t)(row0 + 8) * ldc + col) = v1;
            }
        }
    }
}

// ================= setup / conversion kernels =================

__global__ void build_xs_kernel(const float* __restrict__ features,
                                const int*   __restrict__ captions,
                                const float* __restrict__ table,
                                float* __restrict__ xs)
{
    int idx = blockIdx.x * blockDim.x + threadIdx.x;
    if (idx >= MTOT * EE) return;
    int e = idx % EE;
    int b = (idx / EE) % BB;
    int t = idx / (EE * BB);
    float v;
    if (t == 0) v = features[b * EE + e];
    else {
        int tok = captions[b * TT + (t - 1)];
        v = table[tok * EE + e];
    }
    xs[idx] = v;
}

// f32 -> (hi, lo) bf16 split; src row stride srcld, dst contiguous [rows x cols]
__global__ void convert_split_kernel(const float* __restrict__ src, int srcld, int cols, int total,
                                     __nv_bfloat16* __restrict__ hi, __nv_bfloat16* __restrict__ lo)
{
    int idx = blockIdx.x * blockDim.x + threadIdx.x;
    if (idx >= total) return;
    int r = idx / cols, c = idx % cols;
    float x = src[(size_t)r * srcld + c];
    __nv_bfloat16 h = __float2bfloat16(x);
    hi[idx] = h;
    lo[idx] = __float2bfloat16(x - __bfloat162float(h));
}

__global__ void pack_wcat_kernel(const float* __restrict__ Wih,
                                 const float* __restrict__ Whh,
                                 float* __restrict__ Wcat)
{
    int idx = blockIdx.x * blockDim.x + threadIdx.x;
    if (idx >= H4 * 1024) return;
    int n = idx / 1024, k = idx % 1024;
    Wcat[idx] = (k < 512) ? Wih[n * 512 + k] : Whh[n * 512 + (k - 512)];
}

__global__ void init_state_kernel(const float* __restrict__ features,
                                  float* __restrict__ xh,
                                  float* __restrict__ c)
{
    int idx = blockIdx.x * blockDim.x + threadIdx.x;
    if (idx < BB * 1024) {
        int b = idx / 1024, k = idx % 1024;
        xh[idx] = (k < 512) ? features[b * 512 + k] : 0.0f;
    }
    if (idx < BB * HH) c[idx] = 0.0f;
}

// ============ step GEMM (fp32, split-K partials) — recurrent loop ============
__global__ void __launch_bounds__(128)
gemm_step_kernel(const float* __restrict__ A, int lda,
                 const float* __restrict__ W, int ldw,
                 float* __restrict__ Cpart, int ldc, size_t pstride,
                 int Ksplit)
{
    __shared__ float As[16][68];
    __shared__ float Ws[16][68];
    const int bm = blockIdx.y * 64;
    const int bn = blockIdx.x * 64;
    const int kb = blockIdx.z * Ksplit;
    float* C = Cpart + blockIdx.z * pstride;
    const int tid = threadIdx.x;
    const int tx = tid & 7;
    const int ty = tid >> 3;

    float acc[4][8];
    #pragma unroll
    for (int i = 0; i < 4; i++)
        #pragma unroll
        for (int j = 0; j < 8; j++) acc[i][j] = 0.0f;

    for (int k0 = 0; k0 < Ksplit; k0 += 16) {
        #pragma unroll
        for (int i = 0; i < 2; i++) {
            int idx = tid + i * 128;
            int row = idx >> 2;
            int kq  = idx & 3;
            float4 v = *(const float4*)(A + (size_t)(bm + row) * lda + kb + k0 + kq * 4);
            As[kq*4+0][row] = v.x; As[kq*4+1][row] = v.y;
            As[kq*4+2][row] = v.z; As[kq*4+3][row] = v.w;
            float4 u = *(const float4*)(W + (size_t)(bn + row) * ldw + kb + k0 + kq * 4);
            Ws[kq*4+0][row] = u.x; Ws[kq*4+1][row] = u.y;
            Ws[kq*4+2][row] = u.z; Ws[kq*4+3][row] = u.w;
        }
        __syncthreads();
        #pragma unroll
        for (int k = 0; k < 16; k++) {
            float4 a0 = *(const float4*)&As[k][ty * 4];
            float4 w0 = *(const float4*)&Ws[k][tx * 8];
            float4 w1 = *(const float4*)&Ws[k][tx * 8 + 4];
            float av[4] = {a0.x,a0.y,a0.z,a0.w};
            float wv[8] = {w0.x,w0.y,w0.z,w0.w,w1.x,w1.y,w1.z,w1.w};
            #pragma unroll
            for (int i = 0; i < 4; i++)
                #pragma unroll
                for (int j = 0; j < 8; j++)
                    acc[i][j] = fmaf(av[i], wv[j], acc[i][j]);
        }
        __syncthreads();
    }

    #pragma unroll
    for (int i = 0; i < 4; i++) {
        int gm = bm + ty * 4 + i;
        float4 s0 = make_float4(acc[i][0], acc[i][1], acc[i][2], acc[i][3]);
        float4 s1 = make_float4(acc[i][4], acc[i][5], acc[i][6], acc[i][7]);
        *(float4*)(C + (size_t)gm * ldc + bn + tx * 8)     = s0;
        *(float4*)(C + (size_t)gm * ldc + bn + tx * 8 + 4) = s1;
    }
}

__global__ void softmax_attend_kernel(const float* __restrict__ p0,
                                      const float* __restrict__ p1,
                                      const float* __restrict__ attnx,
                                      const float* __restrict__ b_attn,
                                      const float* __restrict__ cnn,
                                      float* __restrict__ att)
{
    const int b = blockIdx.x;
    const int tid = threadIdx.x;
    __shared__ float red[256];

    float v[8];
    float mx = -1e30f;
    #pragma unroll
    for (int j = 0; j < 8; j++) {
        int col = tid + j * 256;
        size_t o = (size_t)b * AA + col;
        v[j] = p0[o] + p1[o] + attnx[o] + b_attn[col];
        mx = fmaxf(mx, v[j]);
    }
    red[tid] = mx;
    __syncthreads();
    for (int s = 128; s > 0; s >>= 1) {
        if (tid < s) red[tid] = fmaxf(red[tid], red[tid + s]);
        __syncthreads();
    }
    mx = red[0];
    __syncthreads();

    float sum = 0.0f;
    #pragma unroll
    for (int j = 0; j < 8; j++) { v[j] = expf(v[j] - mx); sum += v[j]; }
    red[tid] = sum;
    __syncthreads();
    for (int s = 128; s > 0; s >>= 1) {
        if (tid < s) red[tid] += red[tid + s];
        __syncthreads();
    }
    float inv = 1.0f / red[0];

    #pragma unroll
    for (int j = 0; j < 8; j++) {
        int col = tid + j * 256;
        size_t o = (size_t)b * AA + col;
        att[o] = cnn[o] * v[j] * inv;
    }
}

__global__ void combine_x2_kernel(const float* __restrict__ parts,
                                  const float* __restrict__ attdx,
                                  float* __restrict__ xh)
{
    int idx = blockIdx.x * blockDim.x + threadIdx.x;
    if (idx >= BB * EE) return;
    int b = idx / EE, e = idx % EE;
    float s = attdx[idx];
    #pragma unroll
    for (int p = 0; p < 8; p++) s += parts[(size_t)p * BB * EE + idx];
    xh[b * 1024 + e] = s;
}

__device__ __forceinline__ float sigmoidf_(float x) {
    return 1.0f / (1.0f + expf(-x));
}

__global__ void lstm_pointwise_kernel(const float* __restrict__ gp,
                                      const float* __restrict__ b_ih,
                                      const float* __restrict__ b_hh,
                                      float* __restrict__ xh,
                                      float* __restrict__ c,
                                      float* __restrict__ hid_t)
{
    int idx = blockIdx.x * blockDim.x + threadIdx.x;
    if (idx >= BB * HH) return;
    int b = idx / HH, n = idx % HH;
    float gi = b_ih[n]        + b_hh[n];
    float gf = b_ih[512 + n]  + b_hh[512 + n];
    float gg = b_ih[1024 + n] + b_hh[1024 + n];
    float go = b_ih[1536 + n] + b_hh[1536 + n];
    #pragma unroll
    for (int p = 0; p < 4; p++) {
        const float* base = gp + (size_t)p * BB * H4 + (size_t)b * H4;
        gi += base[n];
        gf += base[512 + n];
        gg += base[1024 + n];
        go += base[1536 + n];
    }
    gi = sigmoidf_(gi);
    gf = sigmoidf_(gf);
    gg = tanhf(gg);
    go = sigmoidf_(go);
    float cc = gf * c[idx] + gi * gg;
    float hh = go * tanhf(cc);
    c[idx] = cc;
    xh[b * 1024 + 512 + n] = hh;
    hid_t[idx] = hh;
}

// ---------------- host ----------------

extern "C" void kernel_launch(void* const* d_in, const int* in_sizes, int n_in,
                              void* d_out, int out_size)
{
    const float* features = (const float*)d_in[0];
    const float* cnn      = (const float*)d_in[1];
    const int*   captions = (const int*)  d_in[2];
    const float* table    = (const float*)d_in[4];
    const float* W_ih     = (const float*)d_in[5];
    const float* W_hh     = (const float*)d_in[6];
    const float* b_ih     = (const float*)d_in[7];
    const float* b_hh     = (const float*)d_in[8];
    const float* W_attn   = (const float*)d_in[9];
    const float* b_attn   = (const float*)d_in[10];
    const float* W_attd   = (const float*)d_in[11];
    const float* b_attd   = (const float*)d_in[12];
    const float* W_out    = (const float*)d_in[13];
    const float* b_out    = (const float*)d_in[14];
    float* out = (float*)d_out;

    float *p_xs, *p_hid, *p_c, *p_xh, *p_attnx, *p_attdx,
          *p_alogp, *p_att, *p_x2p, *p_gp, *p_Wcat;
    __nv_bfloat16 *p_xsh, *p_xsl, *p_hih, *p_hil, *p_Woh, *p_Wol,
                  *p_Wnh, *p_Wnl, *p_Wdh, *p_Wdl;
    cudaGetSymbolAddress((void**)&p_xs,    g_xs);
    cudaGetSymbolAddress((void**)&p_hid,   g_hid);
    cudaGetSymbolAddress((void**)&p_c,     g_c);
    cudaGetSymbolAddress((void**)&p_xh,    g_xh);
    cudaGetSymbolAddress((void**)&p_attnx, g_attnx);
    cudaGetSymbolAddress((void**)&p_attdx, g_attdx);
    cudaGetSymbolAddress((void**)&p_alogp, g_alogp);
    cudaGetSymbolAddress((void**)&p_att,   g_att);
    cudaGetSymbolAddress((void**)&p_x2p,   g_x2p);
    cudaGetSymbolAddress((void**)&p_gp,    g_gp);
    cudaGetSymbolAddress((void**)&p_Wcat,  g_Wcat);
    cudaGetSymbolAddress((void**)&p_xsh,   g_xs_hi);
    cudaGetSymbolAddress((void**)&p_xsl,   g_xs_lo);
    cudaGetSymbolAddress((void**)&p_hih,   g_hid_hi);
    cudaGetSymbolAddress((void**)&p_hil,   g_hid_lo);
    cudaGetSymbolAddress((void**)&p_Woh,   g_Woh);
    cudaGetSymbolAddress((void**)&p_Wol,   g_Wol);
    cudaGetSymbolAddress((void**)&p_Wnh,   g_Wnh);
    cudaGetSymbolAddress((void**)&p_Wnl,   g_Wnl);
    cudaGetSymbolAddress((void**)&p_Wdh,   g_Wdh);
    cudaGetSymbolAddress((void**)&p_Wdl,   g_Wdl);

    cudaFuncSetAttribute(gemm_mma_kernel, cudaFuncAttributeMaxDynamicSharedMemorySize, 65536);

    // Setup
    build_xs_kernel<<<(MTOT*EE + 255)/256, 256>>>(features, captions, table, p_xs);
    pack_wcat_kernel<<<(H4*1024 + 255)/256, 256>>>(W_ih, W_hh, p_Wcat);
    init_state_kernel<<<(BB*1024 + 255)/256, 256>>>(features, p_xh, p_c);

    // bf16 split conversions
    convert_split_kernel<<<(MTOT*EE + 255)/256, 256>>>(p_xs, EE, EE, MTOT*EE, p_xsh, p_xsl);
    convert_split_kernel<<<(AA*EE + 255)/256, 256>>>(W_attn, 1024, EE, AA*EE, p_Wnh, p_Wnl);
    convert_split_kernel<<<(EE*EE + 255)/256, 256>>>(W_attd, 2560, EE, EE*EE, p_Wdh, p_Wdl);
    convert_split_kernel<<<(VV*HH + 255)/256, 256>>>(W_out, HH, HH, VV*HH, p_Woh, p_Wol);

    // attnx = xs @ W_attn[:, :E].T  (all 4096 rows; t=0 block unused)
    gemm_mma_kernel<<<dim3(AA/128, MTOT/128), 256, 65536>>>(
        p_xsh, p_xsl, p_Wnh, p_Wnl, nullptr, p_attnx, AA, AA, EE);
    // attdx = xs @ W_attd[:, :E].T + b_attd
    gemm_mma_kernel<<<dim3(EE/128, MTOT/128), 256, 65536>>>(
        p_xsh, p_xsl, p_Wdh, p_Wdl, b_attd, p_attdx, EE, EE, EE);

    // t = 0: gates = [features|0] @ Wcat.T (split-K4), then LSTM
    gemm_step_kernel<<<dim3(H4/64, BB/64, 4), 128>>>(
        p_xh, 1024, p_Wcat, 1024, p_gp, H4, (size_t)BB*H4, 256);
    lstm_pointwise_kernel<<<(BB*HH + 255)/256, 256>>>(
        p_gp, b_ih, b_hh, p_xh, p_c, p_hid);

    // Recurrent loop
    for (int t = 1; t <= TT; t++) {
        const float* attnx_t = p_attnx + (size_t)t * BB * AA;
        const float* attdx_t = p_attdx + (size_t)t * BB * EE;

        gemm_step_kernel<<<dim3(AA/64, BB/64, 2), 128>>>(
            p_xh + 512, 1024, W_attn + EE, 1024, p_alogp, AA, (size_t)BB*AA, 256);
        softmax_attend_kernel<<<BB, 256>>>(
            p_alogp, p_alogp + BB*AA, attnx_t, b_attn, cnn, p_att);
        gemm_step_kernel<<<dim3(EE/64, BB/64, 8), 128>>>(
            p_att, AA, W_attd + EE, 2560, p_x2p, EE, (size_t)BB*EE, 256);
        combine_x2_kernel<<<(BB*EE + 255)/256, 256>>>(p_x2p, attdx_t, p_xh);
        gemm_step_kernel<<<dim3(H4/64, BB/64, 4), 128>>>(
            p_xh, 1024, p_Wcat, 1024, p_gp, H4, (size_t)BB*H4, 256);
        lstm_pointwise_kernel<<<(BB*HH + 255)/256, 256>>>(
            p_gp, b_ih, b_hh, p_xh, p_c, p_hid + (size_t)t * BB * HH);
    }

    // Output projection (warp-MMA): logits = hidden @ W_out.T + b_out
    convert_split_kernel<<<(MTOT*HH + 255)/256, 256>>>(p_hid, HH, HH, MTOT*HH, p_hih, p_hil);
    gemm_mma_kernel<<<dim3((VV + 127)/128, MTOT/128), 256, 65536>>>(
        p_hih, p_hil, p_Woh, p_Wol, b_out, out, VV, VV, HH);
}

// round 7
// speedup vs baseline: 9.0929x; 1.6983x over previous
#include <cuda_runtime.h>
#include <cuda_bf16.h>
#include <cstdint>
#include <math.h>

// Problem dims
#define BB  128
#define TT  31
#define TP1 32
#define EE  512
#define HH  512
#define H4  2048
#define VV  10000
#define AA  2048
#define MTOT 4096   // (T+1)*B rows

// ---------------- device scratch (static, no allocs) ----------------
__device__ float g_c    [BB*HH];
__device__ float g_attnx[MTOT*AA];
__device__ float g_attdx[MTOT*EE];
__device__ float g_alogp[4*BB*AA];     // attn-logit split-K partials (z=4)
__device__ float g_x2p  [16*BB*EE];    // x2 partials (z=16)
__device__ float g_gp   [8*BB*H4];     // gate partials (z=8)

// bf16 split activation buffers
__device__ __nv_bfloat16 g_xs_hi [MTOT*EE], g_xs_lo [MTOT*EE];
__device__ __nv_bfloat16 g_hid_hi[MTOT*HH], g_hid_lo[MTOT*HH];
__device__ __nv_bfloat16 g_xh_hi [BB*1024], g_xh_lo [BB*1024];   // [x2|h]
__device__ __nv_bfloat16 g_att_hi[BB*AA],   g_att_lo[BB*AA];

// bf16 split weights
__device__ __nv_bfloat16 g_Woh[VV*HH],   g_Wol[VV*HH];     // W_out
__device__ __nv_bfloat16 g_Wnh[AA*EE],   g_Wnl[AA*EE];     // W_attn x-part
__device__ __nv_bfloat16 g_Wn2h[AA*HH],  g_Wn2l[AA*HH];    // W_attn h-part
__device__ __nv_bfloat16 g_Wdh[EE*EE],   g_Wdl[EE*EE];     // W_attd x-part
__device__ __nv_bfloat16 g_Wd2h[EE*AA],  g_Wd2l[EE*AA];    // W_attd a-part
__device__ __nv_bfloat16 g_Wch[H4*1024], g_Wcl[H4*1024];   // [W_ih|W_hh]

// ================= warp-MMA helpers (sm_80+ baseline PTX only) =================
__device__ __forceinline__ uint32_t smem_u32(const void* p) {
    uint32_t a;
    asm("{ .reg .u64 t; cvta.to.shared.u64 t, %1; cvt.u32.u64 %0, t; }" : "=r"(a) : "l"(p));
    return a;
}
__device__ __forceinline__ uint32_t sw128(uint32_t b) { return b ^ ((b >> 3) & 0x70); }

__device__ __forceinline__ void ldsm_x4(uint32_t* r, uint32_t addr) {
    asm volatile("ldmatrix.sync.aligned.m8n8.x4.shared.b16 {%0,%1,%2,%3}, [%4];"
                 : "=r"(r[0]), "=r"(r[1]), "=r"(r[2]), "=r"(r[3]) : "r"(addr));
}
__device__ __forceinline__ void ldsm_x2(uint32_t* r, uint32_t addr) {
    asm volatile("ldmatrix.sync.aligned.m8n8.x2.shared.b16 {%0,%1}, [%2];"
                 : "=r"(r[0]), "=r"(r[1]) : "r"(addr));
}
__device__ __forceinline__ void mma16816(float* d, const uint32_t* a, const uint32_t* b) {
    asm volatile("mma.sync.aligned.m16n8k16.row.col.f32.bf16.bf16.f32 "
                 "{%0,%1,%2,%3}, {%4,%5,%6,%7}, {%8,%9}, {%0,%1,%2,%3};"
                 : "+f"(d[0]), "+f"(d[1]), "+f"(d[2]), "+f"(d[3])
                 : "r"(a[0]), "r"(a[1]), "r"(a[2]), "r"(a[3]), "r"(b[0]), "r"(b[1]));
}

// ============ big warp-MMA split-bf16 GEMM: C = A@B^T (+bias) ============
// A: [M x K] hi/lo, M mult of 128; B: [Ntot x K] hi/lo (row-guarded); K mult of 64.
__global__ void __launch_bounds__(256, 1)
gemm_mma_kernel(const __nv_bfloat16* __restrict__ Ahi,
                const __nv_bfloat16* __restrict__ Alo,
                const __nv_bfloat16* __restrict__ Bhi,
                const __nv_bfloat16* __restrict__ Blo,
                const float* __restrict__ bias,
                float* __restrict__ C, int ldc, int Ntot, int K)
{
    extern __shared__ char smem[];
    const uint32_t sb = smem_u32(smem);
    const int tid = threadIdx.x;
    const int wid = tid >> 5;
    const int lane = tid & 31;
    const int warp_m = wid & 1;
    const int warp_n = wid >> 1;
    const int bm = blockIdx.y * 128;
    const int bn = blockIdx.x * 128;

    float acc[4][4][4];
    #pragma unroll
    for (int i = 0; i < 4; i++)
        #pragma unroll
        for (int j = 0; j < 4; j++)
            #pragma unroll
            for (int r = 0; r < 4; r++) acc[i][j][r] = 0.0f;

    const __nv_bfloat16* srcs[4] = {Ahi, Alo, Bhi, Blo};

    const int nchunks = K >> 6;
    for (int kc = 0; kc < nchunks; kc++) {
        if (kc > 0) __syncthreads();
        #pragma unroll
        for (int t = 0; t < 4; t++) {
            const __nv_bfloat16* src = srcs[t];
            const uint32_t dstbase = t * 16384;
            #pragma unroll
            for (int j = 0; j < 4; j++) {
                int v = tid + j * 256;
                int row = v >> 3, c8 = v & 7;
                uint4 val = make_uint4(0, 0, 0, 0);
                if (t < 2) {
                    val = *(const uint4*)(src + (size_t)(bm + row) * K + kc * 64 + c8 * 8);
                } else {
                    int gn = bn + row;
                    if (gn < Ntot)
                        val = *(const uint4*)(src + (size_t)gn * K + kc * 64 + c8 * 8);
                }
                *(uint4*)(smem + dstbase + sw128(row * 128 + c8 * 16)) = val;
            }
        }
        __syncthreads();

        #pragma unroll
        for (int pass = 0; pass < 3; pass++) {
            const uint32_t abase = sb + ((pass == 2) ? 16384 : 0);
            const uint32_t bbase = sb + 32768 + ((pass == 1) ? 16384 : 0);
            #pragma unroll
            for (int kk = 0; kk < 4; kk++) {
                uint32_t afr[4][4];
                #pragma unroll
                for (int mt = 0; mt < 4; mt++) {
                    int row = warp_m * 64 + mt * 16 + (lane & 15);
                    int kb  = kk * 32 + ((lane >> 4) << 4);
                    ldsm_x4(afr[mt], abase + sw128(row * 128 + kb));
                }
                uint32_t bfr[4][2];
                #pragma unroll
                for (int nt = 0; nt < 4; nt++) {
                    int row = warp_n * 32 + nt * 8 + (lane & 7);
                    int kb  = kk * 32 + (((lane >> 3) & 1) << 4);
                    ldsm_x2(bfr[nt], bbase + sw128(row * 128 + kb));
                }
                #pragma unroll
                for (int mt = 0; mt < 4; mt++)
                    #pragma unroll
                    for (int nt = 0; nt < 4; nt++)
                        mma16816(acc[mt][nt], afr[mt], bfr[nt]);
            }
        }
    }

    const int gid = lane >> 2;
    const int tg  = lane & 3;
    #pragma unroll
    for (int mt = 0; mt < 4; mt++) {
        int row0 = bm + warp_m * 64 + mt * 16 + gid;
        #pragma unroll
        for (int nt = 0; nt < 4; nt++) {
            int col = bn + warp_n * 32 + nt * 8 + tg * 2;
            if (col < Ntot) {
                float b0 = bias ? bias[col] : 0.0f;
                float b1 = bias ? bias[col + 1] : 0.0f;
                float2 v0 = make_float2(acc[mt][nt][0] + b0, acc[mt][nt][1] + b1);
                float2 v1 = make_float2(acc[mt][nt][2] + b0, acc[mt][nt][3] + b1);
                *(float2*)(C + (size_t)row0 * ldc + col) = v0;
                *(float2*)(C + (size_t)(row0 + 8) * ldc + col) = v1;
            }
        }
    }
}

// ============ step warp-MMA GEMM: M=128, split-K, fp32 partials ============
// A: [128 x lda] hi/lo; B: [N x ldb] hi/lo, N mult of 128; Kchunk mult of 64.
// Cpart[z][128][N] += A[:, kb:kb+Kchunk] @ B[:, kb:kb+Kchunk]^T   (3-pass split)
__global__ void __launch_bounds__(256, 1)
gemm_mma_step(const __nv_bfloat16* __restrict__ Ahi,
              const __nv_bfloat16* __restrict__ Alo, int lda,
              const __nv_bfloat16* __restrict__ Bhi,
              const __nv_bfloat16* __restrict__ Blo, int ldb,
              float* __restrict__ Cpart, int N, size_t pstride, int Kchunk)
{
    extern __shared__ char smem[];
    const uint32_t sb = smem_u32(smem);
    const int tid = threadIdx.x;
    const int wid = tid >> 5;
    const int lane = tid & 31;
    const int warp_m = wid & 1;
    const int warp_n = wid >> 1;
    const int bn = blockIdx.x * 128;
    const int kb = blockIdx.z * Kchunk;
    float* C = Cpart + (size_t)blockIdx.z * pstride;

    float acc[4][4][4];
    #pragma unroll
    for (int i = 0; i < 4; i++)
        #pragma unroll
        for (int j = 0; j < 4; j++)
            #pragma unroll
            for (int r = 0; r < 4; r++) acc[i][j][r] = 0.0f;

    const int nchunks = Kchunk >> 6;
    for (int kc = 0; kc < nchunks; kc++) {
        if (kc > 0) __syncthreads();
        // A tiles (hi, lo): 128 x 64
        #pragma unroll
        for (int t = 0; t < 2; t++) {
            const __nv_bfloat16* src = t ? Alo : Ahi;
            const uint32_t dstbase = t * 16384;
            #pragma unroll
            for (int j = 0; j < 4; j++) {
                int v = tid + j * 256;
                int row = v >> 3, c8 = v & 7;
                uint4 val = *(const uint4*)(src + (size_t)row * lda + kb + kc * 64 + c8 * 8);
                *(uint4*)(smem + dstbase + sw128(row * 128 + c8 * 16)) = val;
            }
        }
        // B tiles (hi, lo): 128 x 64
        #pragma unroll
        for (int t = 0; t < 2; t++) {
            const __nv_bfloat16* src = t ? Blo : Bhi;
            const uint32_t dstbase = 32768 + t * 16384;
            #pragma unroll
            for (int j = 0; j < 4; j++) {
                int v = tid + j * 256;
                int row = v >> 3, c8 = v & 7;
                uint4 val = *(const uint4*)(src + (size_t)(bn + row) * ldb + kb + kc * 64 + c8 * 8);
                *(uint4*)(smem + dstbase + sw128(row * 128 + c8 * 16)) = val;
            }
        }
        __syncthreads();

        #pragma unroll
        for (int pass = 0; pass < 3; pass++) {
            const uint32_t abase = sb + ((pass == 2) ? 16384 : 0);
            const uint32_t bbase = sb + 32768 + ((pass == 1) ? 16384 : 0);
            #pragma unroll
            for (int kk = 0; kk < 4; kk++) {
                uint32_t afr[4][4];
                #pragma unroll
                for (int mt = 0; mt < 4; mt++) {
                    int row = warp_m * 64 + mt * 16 + (lane & 15);
                    int kbb = kk * 32 + ((lane >> 4) << 4);
                    ldsm_x4(afr[mt], abase + sw128(row * 128 + kbb));
                }
                uint32_t bfr[4][2];
                #pragma unroll
                for (int nt = 0; nt < 4; nt++) {
                    int row = warp_n * 32 + nt * 8 + (lane & 7);
                    int kbb = kk * 32 + (((lane >> 3) & 1) << 4);
                    ldsm_x2(bfr[nt], bbase + sw128(row * 128 + kbb));
                }
                #pragma unroll
                for (int mt = 0; mt < 4; mt++)
                    #pragma unroll
                    for (int nt = 0; nt < 4; nt++)
                        mma16816(acc[mt][nt], afr[mt], bfr[nt]);
            }
        }
    }

    const int gid = lane >> 2;
    const int tg  = lane & 3;
    #pragma unroll
    for (int mt = 0; mt < 4; mt++) {
        int row0 = warp_m * 64 + mt * 16 + gid;
        #pragma unroll
        for (int nt = 0; nt < 4; nt++) {
            int col = bn + warp_n * 32 + nt * 8 + tg * 2;
            float2 v0 = make_float2(acc[mt][nt][0], acc[mt][nt][1]);
            float2 v1 = make_float2(acc[mt][nt][2], acc[mt][nt][3]);
            *(float2*)(C + (size_t)row0 * N + col) = v0;
            *(float2*)(C + (size_t)(row0 + 8) * N + col) = v1;
        }
    }
}

// ================= setup / pointwise kernels =================

__device__ __forceinline__ void split_write(float x, __nv_bfloat16* hi, __nv_bfloat16* lo, size_t i) {
    __nv_bfloat16 h = __float2bfloat16(x);
    hi[i] = h;
    lo[i] = __float2bfloat16(x - __bfloat162float(h));
}

__global__ void build_xs_kernel(const float* __restrict__ features,
                                const int*   __restrict__ captions,
                                const float* __restrict__ table,
                                __nv_bfloat16* __restrict__ hi,
                                __nv_bfloat16* __restrict__ lo)
{
    int idx = blockIdx.x * blockDim.x + threadIdx.x;
    if (idx >= MTOT * EE) return;
    int e = idx % EE;
    int b = (idx / EE) % BB;
    int t = idx / (EE * BB);
    float v;
    if (t == 0) v = features[b * EE + e];
    else {
        int tok = captions[b * TT + (t - 1)];
        v = table[tok * EE + e];
    }
    split_write(v, hi, lo, idx);
}

// f32 -> (hi, lo) bf16 split; src row stride srcld, dst contiguous [rows x cols]
__global__ void convert_split_kernel(const float* __restrict__ src, int srcld, int cols, int total,
                                     __nv_bfloat16* __restrict__ hi, __nv_bfloat16* __restrict__ lo)
{
    int idx = blockIdx.x * blockDim.x + threadIdx.x;
    if (idx >= total) return;
    int r = idx / cols, c = idx % cols;
    split_write(src[(size_t)r * srcld + c], hi, lo, idx);
}

__global__ void pack_wcat_kernel(const float* __restrict__ Wih,
                                 const float* __restrict__ Whh,
                                 __nv_bfloat16* __restrict__ hi,
                                 __nv_bfloat16* __restrict__ lo)
{
    int idx = blockIdx.x * blockDim.x + threadIdx.x;
    if (idx >= H4 * 1024) return;
    int n = idx / 1024, k = idx % 1024;
    float v = (k < 512) ? Wih[n * 512 + k] : Whh[n * 512 + (k - 512)];
    split_write(v, hi, lo, idx);
}

__global__ void init_state_kernel(const float* __restrict__ features,
                                  __nv_bfloat16* __restrict__ xh_hi,
                                  __nv_bfloat16* __restrict__ xh_lo,
                                  float* __restrict__ c)
{
    int idx = blockIdx.x * blockDim.x + threadIdx.x;
    if (idx < BB * 1024) {
        int b = idx / 1024, k = idx % 1024;
        float v = (k < 512) ? features[b * 512 + k] : 0.0f;
        split_write(v, xh_hi, xh_lo, idx);
    }
    if (idx < BB * HH) c[idx] = 0.0f;
}

// softmax over 2048 (4 partials + attnx + bias), attend, write bf16 hi/lo
__global__ void softmax_attend_kernel(const float* __restrict__ parts,
                                      const float* __restrict__ attnx,
                                      const float* __restrict__ b_attn,
                                      const float* __restrict__ cnn,
                                      __nv_bfloat16* __restrict__ att_hi,
                                      __nv_bfloat16* __restrict__ att_lo)
{
    const int b = blockIdx.x;
    const int tid = threadIdx.x;     // 256
    __shared__ float red[256];

    float v[8];
    float mx = -1e30f;
    #pragma unroll
    for (int j = 0; j < 8; j++) {
        int col = tid + j * 256;
        size_t o = (size_t)b * AA + col;
        float s = attnx[o] + b_attn[col];
        #pragma unroll
        for (int p = 0; p < 4; p++) s += parts[(size_t)p * BB * AA + o];
        v[j] = s;
        mx = fmaxf(mx, s);
    }
    red[tid] = mx;
    __syncthreads();
    for (int s = 128; s > 0; s >>= 1) {
        if (tid < s) red[tid] = fmaxf(red[tid], red[tid + s]);
        __syncthreads();
    }
    mx = red[0];
    __syncthreads();

    float sum = 0.0f;
    #pragma unroll
    for (int j = 0; j < 8; j++) { v[j] = expf(v[j] - mx); sum += v[j]; }
    red[tid] = sum;
    __syncthreads();
    for (int s = 128; s > 0; s >>= 1) {
        if (tid < s) red[tid] += red[tid + s];
        __syncthreads();
    }
    float inv = 1.0f / red[0];

    #pragma unroll
    for (int j = 0; j < 8; j++) {
        int col = tid + j * 256;
        size_t o = (size_t)b * AA + col;
        split_write(cnn[o] * v[j] * inv, att_hi, att_lo, o);
    }
}

// x2 = sum of 16 partials + attdx  -> xh[:, :512] bf16 hi/lo
__global__ void combine_x2_kernel(const float* __restrict__ parts,
                                  const float* __restrict__ attdx,
                                  __nv_bfloat16* __restrict__ xh_hi,
                                  __nv_bfloat16* __restrict__ xh_lo)
{
    int idx = blockIdx.x * blockDim.x + threadIdx.x;
    if (idx >= BB * EE) return;
    int b = idx / EE, e = idx % EE;
    float s = attdx[idx];
    #pragma unroll
    for (int p = 0; p < 16; p++) s += parts[(size_t)p * BB * EE + idx];
    split_write(s, xh_hi, xh_lo, (size_t)b * 1024 + e);
}

__device__ __forceinline__ float sigmoidf_(float x) {
    return 1.0f / (1.0f + expf(-x));
}

// LSTM pointwise: combine 8 gate partials + biases; update c; write h into
// xh[:, 512:] bf16 and hid[t] bf16
__global__ void lstm_pointwise_kernel(const float* __restrict__ gp,
                                      const float* __restrict__ b_ih,
                                      const float* __restrict__ b_hh,
                                      __nv_bfloat16* __restrict__ xh_hi,
                                      __nv_bfloat16* __restrict__ xh_lo,
                                      float* __restrict__ c,
                                      __nv_bfloat16* __restrict__ hid_hi,
                                      __nv_bfloat16* __restrict__ hid_lo)
{
    int idx = blockIdx.x * blockDim.x + threadIdx.x;
    if (idx >= BB * HH) return;
    int b = idx / HH, n = idx % HH;
    float gi = b_ih[n]        + b_hh[n];
    float gf = b_ih[512 + n]  + b_hh[512 + n];
    float gg = b_ih[1024 + n] + b_hh[1024 + n];
    float go = b_ih[1536 + n] + b_hh[1536 + n];
    #pragma unroll
    for (int p = 0; p < 8; p++) {
        const float* base = gp + (size_t)p * BB * H4 + (size_t)b * H4;
        gi += base[n];
        gf += base[512 + n];
        gg += base[1024 + n];
        go += base[1536 + n];
    }
    gi = sigmoidf_(gi);
    gf = sigmoidf_(gf);
    gg = tanhf(gg);
    go = sigmoidf_(go);
    float cc = gf * c[idx] + gi * gg;
    float hh = go * tanhf(cc);
    c[idx] = cc;
    split_write(hh, xh_hi, xh_lo, (size_t)b * 1024 + 512 + n);
    split_write(hh, hid_hi, hid_lo, idx);
}

// ---------------- host ----------------

extern "C" void kernel_launch(void* const* d_in, const int* in_sizes, int n_in,
                              void* d_out, int out_size)
{
    const float* features = (const float*)d_in[0];
    const float* cnn      = (const float*)d_in[1];
    const int*   captions = (const int*)  d_in[2];
    const float* table    = (const float*)d_in[4];
    const float* W_ih     = (const float*)d_in[5];
    const float* W_hh     = (const float*)d_in[6];
    const float* b_ih     = (const float*)d_in[7];
    const float* b_hh     = (const float*)d_in[8];
    const float* W_attn   = (const float*)d_in[9];
    const float* b_attn   = (const float*)d_in[10];
    const float* W_attd   = (const float*)d_in[11];
    const float* b_attd   = (const float*)d_in[12];
    const float* W_out    = (const float*)d_in[13];
    const float* b_out    = (const float*)d_in[14];
    float* out = (float*)d_out;

    float *p_c, *p_attnx, *p_attdx, *p_alogp, *p_x2p, *p_gp;
    __nv_bfloat16 *p_xsh, *p_xsl, *p_hih, *p_hil, *p_xhh, *p_xhl, *p_ath, *p_atl,
                  *p_Woh, *p_Wol, *p_Wnh, *p_Wnl, *p_Wn2h, *p_Wn2l,
                  *p_Wdh, *p_Wdl, *p_Wd2h, *p_Wd2l, *p_Wch, *p_Wcl;
    cudaGetSymbolAddress((void**)&p_c,     g_c);
    cudaGetSymbolAddress((void**)&p_attnx, g_attnx);
    cudaGetSymbolAddress((void**)&p_attdx, g_attdx);
    cudaGetSymbolAddress((void**)&p_alogp, g_alogp);
    cudaGetSymbolAddress((void**)&p_x2p,   g_x2p);
    cudaGetSymbolAddress((void**)&p_gp,    g_gp);
    cudaGetSymbolAddress((void**)&p_xsh,   g_xs_hi);
    cudaGetSymbolAddress((void**)&p_xsl,   g_xs_lo);
    cudaGetSymbolAddress((void**)&p_hih,   g_hid_hi);
    cudaGetSymbolAddress((void**)&p_hil,   g_hid_lo);
    cudaGetSymbolAddress((void**)&p_xhh,   g_xh_hi);
    cudaGetSymbolAddress((void**)&p_xhl,   g_xh_lo);
    cudaGetSymbolAddress((void**)&p_ath,   g_att_hi);
    cudaGetSymbolAddress((void**)&p_atl,   g_att_lo);
    cudaGetSymbolAddress((void**)&p_Woh,   g_Woh);
    cudaGetSymbolAddress((void**)&p_Wol,   g_Wol);
    cudaGetSymbolAddress((void**)&p_Wnh,   g_Wnh);
    cudaGetSymbolAddress((void**)&p_Wnl,   g_Wnl);
    cudaGetSymbolAddress((void**)&p_Wn2h,  g_Wn2h);
    cudaGetSymbolAddress((void**)&p_Wn2l,  g_Wn2l);
    cudaGetSymbolAddress((void**)&p_Wdh,   g_Wdh);
    cudaGetSymbolAddress((void**)&p_Wdl,   g_Wdl);
    cudaGetSymbolAddress((void**)&p_Wd2h,  g_Wd2h);
    cudaGetSymbolAddress((void**)&p_Wd2l,  g_Wd2l);
    cudaGetSymbolAddress((void**)&p_Wch,   g_Wch);
    cudaGetSymbolAddress((void**)&p_Wcl,   g_Wcl);

    cudaFuncSetAttribute(gemm_mma_kernel, cudaFuncAttributeMaxDynamicSharedMemorySize, 65536);
    cudaFuncSetAttribute(gemm_mma_step,   cudaFuncAttributeMaxDynamicSharedMemorySize, 65536);

    // ---- setup: xs (bf16 direct), weight conversions, state init ----
    build_xs_kernel<<<(MTOT*EE + 255)/256, 256>>>(features, captions, table, p_xsh, p_xsl);
    pack_wcat_kernel<<<(H4*1024 + 255)/256, 256>>>(W_ih, W_hh, p_Wch, p_Wcl);
    init_state_kernel<<<(BB*1024 + 255)/256, 256>>>(features, p_xhh, p_xhl, p_c);
    convert_split_kernel<<<(AA*EE + 255)/256, 256>>>(W_attn, 1024, EE, AA*EE, p_Wnh, p_Wnl);
    convert_split_kernel<<<(AA*HH + 255)/256, 256>>>(W_attn + EE, 1024, HH, AA*HH, p_Wn2h, p_Wn2l);
    convert_split_kernel<<<(EE*EE + 255)/256, 256>>>(W_attd, 2560, EE, EE*EE, p_Wdh, p_Wdl);
    convert_split_kernel<<<(EE*AA + 255)/256, 256>>>(W_attd + EE, 2560, AA, EE*AA, p_Wd2h, p_Wd2l);
    convert_split_kernel<<<(VV*HH + 255)/256, 256>>>(W_out, HH, HH, VV*HH, p_Woh, p_Wol);

    // ---- precompute x-dependent attention terms (batched) ----
    gemm_mma_kernel<<<dim3(AA/128, MTOT/128), 256, 65536>>>(
        p_xsh, p_xsl, p_Wnh, p_Wnl, nullptr, p_attnx, AA, AA, EE);
    gemm_mma_kernel<<<dim3(EE/128, MTOT/128), 256, 65536>>>(
        p_xsh, p_xsl, p_Wdh, p_Wdl, b_attd, p_attdx, EE, EE, EE);

    // ---- t = 0: gates = [features|0] @ Wcat^T (split-K8), LSTM ----
    gemm_mma_step<<<dim3(H4/128, 1, 8), 256, 65536>>>(
        p_xhh, p_xhl, 1024, p_Wch, p_Wcl, 1024, p_gp, H4, (size_t)BB*H4, 128);
    lstm_pointwise_kernel<<<(BB*HH + 255)/256, 256>>>(
        p_gp, b_ih, b_hh, p_xhh, p_xhl, p_c, p_hih, p_hil);

    // ---- recurrent loop ----
    for (int t = 1; t <= TT; t++) {
        const float* attnx_t = p_attnx + (size_t)t * BB * AA;
        const float* attdx_t = p_attdx + (size_t)t * BB * EE;

        // attn logits partials: h @ W_attn_h^T  (split-K4, K=512)
        gemm_mma_step<<<dim3(AA/128, 1, 4), 256, 65536>>>(
            p_xhh + 512, p_xhl + 512, 1024, p_Wn2h, p_Wn2l, HH,
            p_alogp, AA, (size_t)BB*AA, 128);
        // softmax + attend -> att bf16
        softmax_attend_kernel<<<BB, 256>>>(p_alogp, attnx_t, b_attn, cnn, p_ath, p_atl);
        // x2 partials: att @ W_attd_a^T  (split-K16, K=2048)
        gemm_mma_step<<<dim3(EE/128, 1, 16), 256, 65536>>>(
            p_ath, p_atl, AA, p_Wd2h, p_Wd2l, AA,
            p_x2p, EE, (size_t)BB*EE, 128);
        // combine -> xh[:, :512] bf16
        combine_x2_kernel<<<(BB*EE + 255)/256, 256>>>(p_x2p, attdx_t, p_xhh, p_xhl);
        // gates partials: [x2|h] @ Wcat^T  (split-K8, K=1024)
        gemm_mma_step<<<dim3(H4/128, 1, 8), 256, 65536>>>(
            p_xhh, p_xhl, 1024, p_Wch, p_Wcl, 1024, p_gp, H4, (size_t)BB*H4, 128);
        // LSTM pointwise
        lstm_pointwise_kernel<<<(BB*HH + 255)/256, 256>>>(
            p_gp, b_ih, b_hh, p_xhh, p_xhl, p_c,
            p_hih + (size_t)t * BB * HH, p_hil + (size_t)t * BB * HH);
    }

    // ---- output projection: logits = hidden @ W_out^T + b_out ----
    gemm_mma_kernel<<<dim3((VV + 127)/128, MTOT/128), 256, 65536>>>(
        p_hih, p_hil, p_Woh, p_Wol, b_out, out, VV, VV, HH);
}